// round 8
// baseline (speedup 1.0000x reference)
#include <cuda_runtime.h>

#define N_CHROM 23
#define BINS    5000
#define NB      16
#define NS      512
#define EOS_DIM 512
#define BIN_DIM 256
#define VOCAB   (N_CHROM * BINS)        // 115000
#define NSAMP   (N_CHROM * NB * NS)     // 188416
#define OCC     4
#define GRID    (148 * OCC)             // 592
#define NWARPS  (GRID * 8)              // 4736
#define NUNITS  (VOCAB / 2)             // 57500 two-row units
#define EOS_B0  (GRID - 46)             // eos on high block ids

// ---- scratch (device globals) ----
__device__ __align__(16) float g_M[3 * BIN_DIM];     // W_fc1 @ W_bin  [3,256]
__device__ __align__(16) float g_Meos[3 * EOS_DIM];  // W_fc2 @ W_eos  [3,512]
__device__ float    g_cbias[4];
__device__ float4   g_E[NB * N_CHROM];
__device__ float4   g_P[VOCAB];
__device__ unsigned g_bar;              // monotone barrier counter (zero-init)

__device__ __forceinline__ void grid_bar(unsigned target) {
    __syncthreads();
    if (threadIdx.x == 0) {
        __threadfence();
        unsigned prev = atomicAdd(&g_bar, 1u);
        if (prev + 1u < target) {
            while (*(volatile unsigned*)&g_bar < target) __nanosleep(32);
        }
        __threadfence();
    }
    __syncthreads();
}

__device__ __forceinline__ float dot4(float4 a, float4 m) {
    return a.x*m.x + a.y*m.y + a.z*m.z + a.w*m.w;
}

__global__ void __launch_bounds__(256, OCC)
k_fused(const float*  __restrict__ eos_emb,   // [16,23,512]
        const int4*   __restrict__ sampled,   // [23,16,512] as quads
        const int4*   __restrict__ targets,
        const float4* __restrict__ tbl,       // [115000,64] float4
        const float*  __restrict__ Wbin,      // [512,256]
        const float*  __restrict__ Weos,      // [512,512]
        const float*  __restrict__ beos,      // [512]
        const float*  __restrict__ Wfc,       // [3,1024]
        const float*  __restrict__ bfc,       // [3]
        float* __restrict__ out,
        int write_targets) {
    const int bid  = blockIdx.x;
    const int tid  = threadIdx.x;
    const int lane = tid & 31;
    const int warp = tid >> 5;
    const int gw   = bid * 8 + warp;            // 0..4735
    const int k    = lane & 15;                 // lane within row
    const int j    = lane >> 4;                 // row within unit (0/1)

    __shared__ float  s[3][8][32];
    __shared__ float4 sM[3 * 64];

    // ---- early loads: first sweep unit in flight before/through prep ----
    const int cnt = (NUNITS - 1 - gw) / NWARPS + 1;   // 12 or 13
    float4 A0, A1, A2, A3;
    {
        const float4* b0 = tbl + (size_t)gw * 128 + j * 64 + k;
        A0 = __ldcg(b0);
        A1 = __ldcg(b0 + 16);
        A2 = __ldcg(b0 + 32);
        A3 = __ldcg(b0 + 48);
    }

    // ================= Phase 0: fold the weight chain =================
    if (bid < 24) {
        bool is_eos = (bid < 16);
        int  e      = (is_eos ? bid * 32 : (bid - 16) * 32) + lane;
        int  stride = is_eos ? 512 : 256;
        const float* W = is_eos ? Weos : Wbin;
        int  fc     = is_eos ? 512 : 0;

        float a0 = 0.f, a1 = 0.f, a2 = 0.f;
        int dbeg = warp * 64;
#pragma unroll 16
        for (int d = dbeg; d < dbeg + 64; d++) {
            float w = W[d * stride + e];
            a0 += __ldg(&Wfc[fc + d])        * w;   // Wfc is a true input: nc OK
            a1 += __ldg(&Wfc[1024 + fc + d]) * w;
            a2 += __ldg(&Wfc[2048 + fc + d]) * w;
        }
        s[0][warp][lane] = a0;
        s[1][warp][lane] = a1;
        s[2][warp][lane] = a2;
        __syncthreads();
#pragma unroll
        for (int off = 4; off; off >>= 1) {
            if (warp < off) {
                s[0][warp][lane] += s[0][warp + off][lane];
                s[1][warp][lane] += s[1][warp + off][lane];
                s[2][warp][lane] += s[2][warp + off][lane];
            }
            __syncthreads();
        }
        if (warp == 0) {
            if (is_eos) {
                g_Meos[e]        = s[0][0][lane];
                g_Meos[512 + e]  = s[1][0][lane];
                g_Meos[1024 + e] = s[2][0][lane];
            } else {
                g_M[e]           = s[0][0][lane];
                g_M[256 + e]     = s[1][0][lane];
                g_M[512 + e]     = s[2][0][lane];
            }
        }
    } else if (bid == 24 && tid < 32) {
        float a0 = 0.f, a1 = 0.f, a2 = 0.f;
#pragma unroll
        for (int d = lane; d < 512; d += 32) {
            float v = beos[d];
            a0 += Wfc[512 + d]        * v;
            a1 += Wfc[1024 + 512 + d] * v;
            a2 += Wfc[2048 + 512 + d] * v;
        }
#pragma unroll
        for (int o = 16; o; o >>= 1) {
            a0 += __shfl_down_sync(0xffffffffu, a0, o);
            a1 += __shfl_down_sync(0xffffffffu, a1, o);
            a2 += __shfl_down_sync(0xffffffffu, a2, o);
        }
        if (lane == 0) {
            g_cbias[0] = a0 + bfc[0];
            g_cbias[1] = a1 + bfc[1];
            g_cbias[2] = a2 + bfc[2];
        }
    }

    grid_bar(GRID);   // ---- barrier A: g_M / g_Meos / g_cbias ready ----

    // stage folded bin matrix into smem (coherent loads; g_M written this launch)
    if (tid < 192) sM[tid] = reinterpret_cast<const float4*>(g_M)[tid];
    __syncthreads();

    // ================= Phase 1a: eos dot (high blocks) =================
    if (bid >= EOS_B0) {
        int w = (bid - EOS_B0) * 8 + warp;   // 0..367 = b*23 + c
        const float4* row = reinterpret_cast<const float4*>(eos_emb + (size_t)w * EOS_DIM);
        const float4* M0  = reinterpret_cast<const float4*>(g_Meos);
        const float4* M1  = reinterpret_cast<const float4*>(g_Meos + EOS_DIM);
        const float4* M2  = reinterpret_cast<const float4*>(g_Meos + 2 * EOS_DIM);
        float s0 = 0.f, s1 = 0.f, s2 = 0.f;
#pragma unroll
        for (int i = lane; i < EOS_DIM / 4; i += 32) {
            float4 x = row[i];
            float4 m0 = M0[i], m1 = M1[i], m2 = M2[i];
            s0 += x.x*m0.x + x.y*m0.y + x.z*m0.z + x.w*m0.w;
            s1 += x.x*m1.x + x.y*m1.y + x.z*m1.z + x.w*m1.w;
            s2 += x.x*m2.x + x.y*m2.y + x.z*m2.z + x.w*m2.w;
        }
#pragma unroll
        for (int o = 16; o; o >>= 1) {
            s0 += __shfl_down_sync(0xffffffffu, s0, o);
            s1 += __shfl_down_sync(0xffffffffu, s1, o);
            s2 += __shfl_down_sync(0xffffffffu, s2, o);
        }
        if (lane == 0)
            g_E[w] = make_float4(s0 + g_cbias[0], s1 + g_cbias[1], s2 + g_cbias[2], 0.f);
    }

    // ===== Phase 1b: table sweep — 16-lane rows, depth-2 reg buffer =====
    {
        int p = gw;
        for (int i = 1; i < cnt; i++) {
            const int pn = gw + i * NWARPS;
            const float4* nb = tbl + (size_t)pn * 128 + j * 64 + k;
            float4 B0 = __ldcg(nb);
            float4 B1 = __ldcg(nb + 16);
            float4 B2 = __ldcg(nb + 32);
            float4 B3 = __ldcg(nb + 48);

            float a0 = dot4(A0, sM[k])       + dot4(A1, sM[k + 16])
                     + dot4(A2, sM[k + 32])  + dot4(A3, sM[k + 48]);
            float a1 = dot4(A0, sM[64 + k])  + dot4(A1, sM[80 + k])
                     + dot4(A2, sM[96 + k])  + dot4(A3, sM[112 + k]);
            float a2 = dot4(A0, sM[128 + k]) + dot4(A1, sM[144 + k])
                     + dot4(A2, sM[160 + k]) + dot4(A3, sM[176 + k]);
#pragma unroll
            for (int o = 8; o; o >>= 1) {    // reduce within 16-lane groups
                a0 += __shfl_xor_sync(0xffffffffu, a0, o);
                a1 += __shfl_xor_sync(0xffffffffu, a1, o);
                a2 += __shfl_xor_sync(0xffffffffu, a2, o);
            }
            if (k == 0)                      // lanes 0 and 16 store rows 2p, 2p+1
                g_P[2 * p + j] = make_float4(a0, a1, a2, 0.f);

            A0 = B0; A1 = B1; A2 = B2; A3 = B3;
            p = pn;
        }
        // epilogue: last unit
        {
            float a0 = dot4(A0, sM[k])       + dot4(A1, sM[k + 16])
                     + dot4(A2, sM[k + 32])  + dot4(A3, sM[k + 48]);
            float a1 = dot4(A0, sM[64 + k])  + dot4(A1, sM[80 + k])
                     + dot4(A2, sM[96 + k])  + dot4(A3, sM[112 + k]);
            float a2 = dot4(A0, sM[128 + k]) + dot4(A1, sM[144 + k])
                     + dot4(A2, sM[160 + k]) + dot4(A3, sM[176 + k]);
#pragma unroll
            for (int o = 8; o; o >>= 1) {
                a0 += __shfl_xor_sync(0xffffffffu, a0, o);
                a1 += __shfl_xor_sync(0xffffffffu, a1, o);
                a2 += __shfl_xor_sync(0xffffffffu, a2, o);
            }
            if (k == 0)
                g_P[2 * p + j] = make_float4(a0, a1, a2, 0.f);
        }
    }

    grid_bar(2 * GRID);   // ---- barrier B: g_P / g_E ready ----

    // ================= Phase 2: gather + relu + emit ==================
    {
        int q = bid * 80 + tid;
        if (tid < 80 && q < NSAMP / 4) {
            int i = q * 4;
            int c = i / (NB * NS);
            int b = (i - c * (NB * NS)) / NS;

            int4 sv = sampled[q];
            int  vb = c * BINS;
            float4 p0 = g_P[vb + sv.x];
            float4 p1 = g_P[vb + sv.y];
            float4 p2 = g_P[vb + sv.z];
            float4 p3 = g_P[vb + sv.w];
            float4 e  = g_E[b * N_CHROM + c];

            float4* o4 = reinterpret_cast<float4*>(out + 12 * (size_t)q);
            o4[0] = make_float4(fmaxf(p0.x + e.x, 0.f), fmaxf(p0.y + e.y, 0.f),
                                fmaxf(p0.z + e.z, 0.f), fmaxf(p1.x + e.x, 0.f));
            o4[1] = make_float4(fmaxf(p1.y + e.y, 0.f), fmaxf(p1.z + e.z, 0.f),
                                fmaxf(p2.x + e.x, 0.f), fmaxf(p2.y + e.y, 0.f));
            o4[2] = make_float4(fmaxf(p2.z + e.z, 0.f), fmaxf(p3.x + e.x, 0.f),
                                fmaxf(p3.y + e.y, 0.f), fmaxf(p3.z + e.z, 0.f));

            if (write_targets) {
                int4 tv = targets[q];
                reinterpret_cast<float4*>(out + 3 * NSAMP)[q] =
                    make_float4((float)tv.x, (float)tv.y, (float)tv.z, (float)tv.w);
            }
        }
    }

    // ---- final arrive: last arrival resets counter for graph replay ----
    __syncthreads();
    if (tid == 0) {
        unsigned prev = atomicAdd(&g_bar, 1u);
        if (prev + 1u == 3u * GRID) atomicExch(&g_bar, 0u);
    }
}

// ---------------------------------------------------------------------------
extern "C" void kernel_launch(void* const* d_in, const int* in_sizes, int n_in,
                              void* d_out, int out_size) {
    const float*  eos_emb = (const float*) d_in[0];
    const int4*   sampled = (const int4*)  d_in[1];
    const int4*   targets = (const int4*)  d_in[2];
    const float4* tbl     = (const float4*)d_in[3];
    const float*  Wbin    = (const float*) d_in[4];
    const float*  Weos    = (const float*) d_in[5];
    const float*  beos    = (const float*) d_in[6];
    const float*  Wfc     = (const float*) d_in[7];
    const float*  bfc     = (const float*) d_in[8];
    float* out = (float*)d_out;

    int write_targets = (out_size >= 4 * NSAMP) ? 1 : 0;
    k_fused<<<GRID, 256>>>(eos_emb, sampled, targets, tbl,
                           Wbin, Weos, beos, Wfc, bfc, out, write_targets);
}

// round 9
// speedup vs baseline: 1.4317x; 1.4317x over previous
#include <cuda_runtime.h>

#define N_CHROM 23
#define BINS    5000
#define NB      16
#define NS      512
#define EOS_DIM 512
#define BIN_DIM 256
#define VOCAB   (N_CHROM * BINS)        // 115000
#define NSAMP   (N_CHROM * NB * NS)     // 188416
#define GRID    592                     // 148 SMs * 4 resident blocks
#define NWARPS  (GRID * 8)              // 4736
#define NUNITS  (VOCAB / 2)             // 57500 two-row units
#define EOS_B0  (GRID - 46)             // eos handled by high block ids

// ---- scratch (device globals) ----
__device__ float    g_M[3 * BIN_DIM];      // W_fc1 @ W_bin  [3,256]
__device__ float    g_Meos[3 * EOS_DIM];   // W_fc2 @ W_eos  [3,512]
__device__ float    g_cbias[4];
__device__ float4   g_E[NB * N_CHROM];
__device__ float4   g_P[VOCAB];
__device__ unsigned g_bar;                 // monotone barrier counter (zero-init)

__device__ __forceinline__ void grid_bar(unsigned target) {
    __syncthreads();
    if (threadIdx.x == 0) {
        __threadfence();
        unsigned prev = atomicAdd(&g_bar, 1u);
        if (prev + 1u < target) {
            while (*(volatile unsigned*)&g_bar < target) __nanosleep(32);
        }
        __threadfence();
    }
    __syncthreads();
}

__device__ __forceinline__ float dot8(float4 a, float4 b, float4 m, float4 mb) {
    return a.x*m.x + a.y*m.y + a.z*m.z + a.w*m.w
         + b.x*mb.x + b.y*mb.y + b.z*mb.z + b.w*mb.w;
}

__global__ void __launch_bounds__(256, 4)
k_fused(const float*  __restrict__ eos_emb,   // [16,23,512]
        const int4*   __restrict__ sampled,   // [23,16,512] as quads
        const int4*   __restrict__ targets,
        const float4* __restrict__ tbl,       // [115000,64] float4
        const float*  __restrict__ Wbin,      // [512,256]
        const float*  __restrict__ Weos,      // [512,512]
        const float*  __restrict__ beos,      // [512]
        const float*  __restrict__ Wfc,       // [3,1024]
        const float*  __restrict__ bfc,       // [3]
        float* __restrict__ out,
        int write_targets) {
    const int bid  = blockIdx.x;
    const int tid  = threadIdx.x;
    const int lane = tid & 31;
    const int warp = tid >> 5;

    __shared__ float  s[3][8][32];
    __shared__ float4 sM[3 * 64];

    // ================= Phase 0: fold the weight chain =================
    if (bid < 24) {
        bool is_eos = (bid < 16);
        int  e      = (is_eos ? bid * 32 : (bid - 16) * 32) + lane;
        int  stride = is_eos ? 512 : 256;
        const float* W = is_eos ? Weos : Wbin;
        int  fc     = is_eos ? 512 : 0;

        float a0 = 0.f, a1 = 0.f, a2 = 0.f;
        int dbeg = warp * 64;
#pragma unroll 16
        for (int d = dbeg; d < dbeg + 64; d++) {
            float w = W[d * stride + e];
            a0 += __ldg(&Wfc[fc + d])        * w;
            a1 += __ldg(&Wfc[1024 + fc + d]) * w;
            a2 += __ldg(&Wfc[2048 + fc + d]) * w;
        }
        s[0][warp][lane] = a0;
        s[1][warp][lane] = a1;
        s[2][warp][lane] = a2;
        __syncthreads();
#pragma unroll
        for (int off = 4; off; off >>= 1) {
            if (warp < off) {
                s[0][warp][lane] += s[0][warp + off][lane];
                s[1][warp][lane] += s[1][warp + off][lane];
                s[2][warp][lane] += s[2][warp + off][lane];
            }
            __syncthreads();
        }
        if (warp == 0) {
            if (is_eos) {
                g_Meos[e]        = s[0][0][lane];
                g_Meos[512 + e]  = s[1][0][lane];
                g_Meos[1024 + e] = s[2][0][lane];
            } else {
                g_M[e]           = s[0][0][lane];
                g_M[256 + e]     = s[1][0][lane];
                g_M[512 + e]     = s[2][0][lane];
            }
        }
    } else if (bid == 24 && tid < 32) {
        float a0 = 0.f, a1 = 0.f, a2 = 0.f;
#pragma unroll
        for (int d = lane; d < 512; d += 32) {
            float v = beos[d];
            a0 += Wfc[512 + d]        * v;
            a1 += Wfc[1024 + 512 + d] * v;
            a2 += Wfc[2048 + 512 + d] * v;
        }
#pragma unroll
        for (int o = 16; o; o >>= 1) {
            a0 += __shfl_down_sync(0xffffffffu, a0, o);
            a1 += __shfl_down_sync(0xffffffffu, a1, o);
            a2 += __shfl_down_sync(0xffffffffu, a2, o);
        }
        if (lane == 0) {
            g_cbias[0] = a0 + bfc[0];
            g_cbias[1] = a1 + bfc[1];
            g_cbias[2] = a2 + bfc[2];
        }
    }

    grid_bar(GRID);   // ---- barrier A: g_M / g_Meos / g_cbias ready ----

    if (tid < 192) sM[tid] = reinterpret_cast<const float4*>(g_M)[tid];
    __syncthreads();

    // ================= Phase 1a: eos dot (high blocks) =================
    if (bid >= EOS_B0) {
        int w = (bid - EOS_B0) * 8 + warp;   // 0..367 = b*23 + c
        const float4* row = reinterpret_cast<const float4*>(eos_emb + (size_t)w * EOS_DIM);
        const float4* M0  = reinterpret_cast<const float4*>(g_Meos);
        const float4* M1  = reinterpret_cast<const float4*>(g_Meos + EOS_DIM);
        const float4* M2  = reinterpret_cast<const float4*>(g_Meos + 2 * EOS_DIM);
        float s0 = 0.f, s1 = 0.f, s2 = 0.f;
#pragma unroll
        for (int i = lane; i < EOS_DIM / 4; i += 32) {
            float4 x = row[i];
            float4 m0 = M0[i], m1 = M1[i], m2 = M2[i];
            s0 += x.x*m0.x + x.y*m0.y + x.z*m0.z + x.w*m0.w;
            s1 += x.x*m1.x + x.y*m1.y + x.z*m1.z + x.w*m1.w;
            s2 += x.x*m2.x + x.y*m2.y + x.z*m2.z + x.w*m2.w;
        }
#pragma unroll
        for (int o = 16; o; o >>= 1) {
            s0 += __shfl_down_sync(0xffffffffu, s0, o);
            s1 += __shfl_down_sync(0xffffffffu, s1, o);
            s2 += __shfl_down_sync(0xffffffffu, s2, o);
        }
        if (lane == 0)
            g_E[w] = make_float4(s0 + g_cbias[0], s1 + g_cbias[1], s2 + g_cbias[2], 0.f);
    }

    // ===== Phase 1b: table sweep — L2-cached loads (cross-replay reuse) =====
    {
        const int gw = bid * 8 + warp;                // 0..4735, always < NUNITS
        int p = gw;

        float4 A0, A1, A2, A3;
        {
            const float4* b0 = tbl + (size_t)p * 128;
            A0 = __ldcg(b0 + lane);
            A1 = __ldcg(b0 + 32 + lane);
            A2 = __ldcg(b0 + 64 + lane);
            A3 = __ldcg(b0 + 96 + lane);
        }
        while (true) {
            int  pn   = p + NWARPS;
            bool more = pn < NUNITS;
            float4 B0, B1, B2, B3;
            if (more) {
                const float4* nb = tbl + (size_t)pn * 128;
                B0 = __ldcg(nb + lane);           // prefetch next unit
                B1 = __ldcg(nb + 32 + lane);
                B2 = __ldcg(nb + 64 + lane);
                B3 = __ldcg(nb + 96 + lane);
            }
            // ---- row 0 of unit (A0,A1) ----
            float r0 = dot8(A0, A1, sM[lane],       sM[32 + lane]);
            float r1 = dot8(A0, A1, sM[64 + lane],  sM[96 + lane]);
            float r2 = dot8(A0, A1, sM[128 + lane], sM[160 + lane]);
#pragma unroll
            for (int o = 16; o; o >>= 1) {
                r0 += __shfl_xor_sync(0xffffffffu, r0, o);
                r1 += __shfl_xor_sync(0xffffffffu, r1, o);
                r2 += __shfl_xor_sync(0xffffffffu, r2, o);
            }
            // ---- row 1 of unit (A2,A3) ----
            float t0 = dot8(A2, A3, sM[lane],       sM[32 + lane]);
            float t1 = dot8(A2, A3, sM[64 + lane],  sM[96 + lane]);
            float t2 = dot8(A2, A3, sM[128 + lane], sM[160 + lane]);
#pragma unroll
            for (int o = 16; o; o >>= 1) {
                t0 += __shfl_xor_sync(0xffffffffu, t0, o);
                t1 += __shfl_xor_sync(0xffffffffu, t1, o);
                t2 += __shfl_xor_sync(0xffffffffu, t2, o);
            }
            if (lane < 2) {
                float4 v = (lane == 0) ? make_float4(r0, r1, r2, 0.f)
                                       : make_float4(t0, t1, t2, 0.f);
                g_P[2 * p + lane] = v;
            }
            if (!more) break;
            A0 = B0; A1 = B1; A2 = B2; A3 = B3;
            p = pn;
        }
    }

    grid_bar(2 * GRID);   // ---- barrier B: g_P / g_E ready ----

    // ================= Phase 2: gather + relu + emit ==================
    {
        int q = bid * 80 + tid;                 // 80 quads/block, coalesced
        if (tid < 80 && q < NSAMP / 4) {
            int i = q * 4;
            int c = i / (NB * NS);
            int b = (i - c * (NB * NS)) / NS;

            int4 sv = sampled[q];
            int  vb = c * BINS;
            float4 p0 = g_P[vb + sv.x];
            float4 p1 = g_P[vb + sv.y];
            float4 p2 = g_P[vb + sv.z];
            float4 p3 = g_P[vb + sv.w];
            float4 e  = g_E[b * N_CHROM + c];

            float4* o4 = reinterpret_cast<float4*>(out + 12 * (size_t)q);
            o4[0] = make_float4(fmaxf(p0.x + e.x, 0.f), fmaxf(p0.y + e.y, 0.f),
                                fmaxf(p0.z + e.z, 0.f), fmaxf(p1.x + e.x, 0.f));
            o4[1] = make_float4(fmaxf(p1.y + e.y, 0.f), fmaxf(p1.z + e.z, 0.f),
                                fmaxf(p2.x + e.x, 0.f), fmaxf(p2.y + e.y, 0.f));
            o4[2] = make_float4(fmaxf(p2.z + e.z, 0.f), fmaxf(p3.x + e.x, 0.f),
                                fmaxf(p3.y + e.y, 0.f), fmaxf(p3.z + e.z, 0.f));

            if (write_targets) {
                int4 tv = targets[q];
                reinterpret_cast<float4*>(out + 3 * NSAMP)[q] =
                    make_float4((float)tv.x, (float)tv.y, (float)tv.z, (float)tv.w);
            }
        }
    }

    // ---- final arrive: last arrival resets counter for graph replay ----
    __syncthreads();
    if (tid == 0) {
        unsigned prev = atomicAdd(&g_bar, 1u);
        if (prev + 1u == 3u * GRID) atomicExch(&g_bar, 0u);
    }
}

// ---------------------------------------------------------------------------
extern "C" void kernel_launch(void* const* d_in, const int* in_sizes, int n_in,
                              void* d_out, int out_size) {
    const float*  eos_emb = (const float*) d_in[0];
    const int4*   sampled = (const int4*)  d_in[1];
    const int4*   targets = (const int4*)  d_in[2];
    const float4* tbl     = (const float4*)d_in[3];
    const float*  Wbin    = (const float*) d_in[4];
    const float*  Weos    = (const float*) d_in[5];
    const float*  beos    = (const float*) d_in[6];
    const float*  Wfc     = (const float*) d_in[7];
    const float*  bfc     = (const float*) d_in[8];
    float* out = (float*)d_out;

    int write_targets = (out_size >= 4 * NSAMP) ? 1 : 0;
    k_fused<<<GRID, 256>>>(eos_emb, sampled, targets, tbl,
                           Wbin, Weos, beos, Wfc, bfc, out, write_targets);
}